// round 1
// baseline (speedup 1.0000x reference)
#include <cuda_runtime.h>
#include <cstdint>

#define MAX_NODES 50048
#define MAX_EDGES 1600000

// Scratch (static __device__ arrays — allocation-free per harness rules)
__device__ float    g_hn[(size_t)MAX_NODES * 128];    // node projections
__device__ float    g_msum[(size_t)MAX_NODES * 256];  // [0:128)=sum hn[src], [128:256)=sum he
__device__ unsigned g_deg[MAX_NODES];
__device__ float    g_WnT[256 * 128];                 // Wn transposed (k-major)
__device__ float    g_WrT[256 * 256];                 // Wr transposed (k-major)

__device__ __forceinline__ void red_add_v4(float* p, float4 v) {
    asm volatile("red.global.add.v4.f32 [%0], {%1,%2,%3,%4};"
                 :: "l"(p), "f"(v.x), "f"(v.y), "f"(v.z), "f"(v.w) : "memory");
}
__device__ __forceinline__ void red_add_u32(unsigned* p, unsigned v) {
    asm volatile("red.global.add.u32 [%0], %1;" :: "l"(p), "r"(v) : "memory");
}

// ---------------------------------------------------------------------------
// K0: zero accumulators
// ---------------------------------------------------------------------------
__global__ void zero_kernel(int n_nodes) {
    int stride = gridDim.x * blockDim.x;
    int tid = blockIdx.x * blockDim.x + threadIdx.x;
    int total4 = n_nodes * 64;  // msum in float4 units
    float4 z = make_float4(0.f, 0.f, 0.f, 0.f);
    for (int i = tid; i < total4; i += stride)
        reinterpret_cast<float4*>(g_msum)[i] = z;
    for (int i = tid; i < n_nodes; i += stride)
        g_deg[i] = 0u;
}

// ---------------------------------------------------------------------------
// K1: transpose Wn -> WnT and Wr -> WrT  (tiny)
// ---------------------------------------------------------------------------
__global__ void prep_kernel(const float* __restrict__ Wn, const float* __restrict__ Wr) {
    int i = blockIdx.x * blockDim.x + threadIdx.x;
    if (i < 128 * 256) {                 // Wn [128,256]
        int j = i >> 8, k = i & 255;
        g_WnT[k * 128 + j] = Wn[i];
    }
    int i2 = i - 128 * 256;
    if (i2 >= 0 && i2 < 256 * 256) {     // Wr [256,256]
        int j = i2 >> 8, k = i2 & 255;
        g_WrT[k * 256 + j] = Wr[i2];
    }
}

// ---------------------------------------------------------------------------
// K2: hn = x @ Wn^T + bn     (tile: 32 nodes x 128 outputs per CTA)
// ---------------------------------------------------------------------------
__global__ __launch_bounds__(256) void hn_kernel(const float* __restrict__ x,
                                                 const float* __restrict__ bn,
                                                 int n_nodes) {
    __shared__ float xs[32][256];
    int node0 = blockIdx.x * 32;
    int tid = threadIdx.x;

    // load x tile (float4)
    for (int i = tid; i < 32 * 64; i += 256) {
        int n = i >> 6, c = i & 63;
        float4 v = make_float4(0.f, 0.f, 0.f, 0.f);
        if (node0 + n < n_nodes)
            v = reinterpret_cast<const float4*>(x + (size_t)(node0 + n) * 256)[c];
        *reinterpret_cast<float4*>(&xs[n][4 * c]) = v;
    }
    __syncthreads();

    int jq = tid & 31;   // output quad: j = 4*jq .. 4*jq+3   (128 outputs)
    int ng = tid >> 5;   // node group of 4: nodes ng*4 .. ng*4+3

    float4 bq = *reinterpret_cast<const float4*>(&bn[4 * jq]);
    float4 acc[4];
#pragma unroll
    for (int r = 0; r < 4; r++) acc[r] = bq;

#pragma unroll 4
    for (int k = 0; k < 256; k++) {
        float4 w = *reinterpret_cast<const float4*>(&g_WnT[(size_t)k * 128 + 4 * jq]);
#pragma unroll
        for (int r = 0; r < 4; r++) {
            float t = xs[ng * 4 + r][k];
            acc[r].x += w.x * t; acc[r].y += w.y * t;
            acc[r].z += w.z * t; acc[r].w += w.w * t;
        }
    }
#pragma unroll
    for (int r = 0; r < 4; r++) {
        int n = node0 + ng * 4 + r;
        if (n < n_nodes)
            *reinterpret_cast<float4*>(&g_hn[(size_t)n * 128 + 4 * jq]) = acc[r];
    }
}

// ---------------------------------------------------------------------------
// K3: edge kernel — one warp per edge:
//     he = We @ ez[e] + be;  msum[dst][0:128)   += hn[src]
//                            msum[dst][128:256) += he;  deg[dst] += 1
// ---------------------------------------------------------------------------
__global__ __launch_bounds__(256) void edge_kernel(const float* __restrict__ ez,
                                                   const int* __restrict__ src,
                                                   const int* __restrict__ dst,
                                                   const float* __restrict__ We,
                                                   const float* __restrict__ be,
                                                   int n_edges) {
    __shared__ float WeT_s[64][128];   // 32 KB, transposed k-major
    __shared__ float be_s[128];

    for (int i = threadIdx.x; i < 128 * 64; i += blockDim.x) {
        int j = i >> 6, k = i & 63;    // We row-major [128,64]
        WeT_s[k][j] = We[i];
    }
    if (threadIdx.x < 128) be_s[threadIdx.x] = be[threadIdx.x];
    __syncthreads();

    int lane = threadIdx.x & 31;
    int warp = blockIdx.x * (blockDim.x >> 5) + (threadIdx.x >> 5);
    int nwarps = gridDim.x * (blockDim.x >> 5);

    float4 be4 = *reinterpret_cast<const float4*>(&be_s[4 * lane]);

    for (int e = warp; e < n_edges; e += nwarps) {
        const float* ezr = ez + (size_t)e * 64;
        float ez0 = ezr[lane];
        float ez1 = ezr[lane + 32];
        int s = src[e];
        int d = dst[e];

        float4 he = be4;
#pragma unroll
        for (int k = 0; k < 32; k++) {
            float ezk = __shfl_sync(0xffffffffu, ez0, k);
            float4 w = *reinterpret_cast<const float4*>(&WeT_s[k][4 * lane]);
            he.x += w.x * ezk; he.y += w.y * ezk;
            he.z += w.z * ezk; he.w += w.w * ezk;
        }
#pragma unroll
        for (int k = 0; k < 32; k++) {
            float ezk = __shfl_sync(0xffffffffu, ez1, k);
            float4 w = *reinterpret_cast<const float4*>(&WeT_s[k + 32][4 * lane]);
            he.x += w.x * ezk; he.y += w.y * ezk;
            he.z += w.z * ezk; he.w += w.w * ezk;
        }

        float4 hn4 = *reinterpret_cast<const float4*>(&g_hn[(size_t)s * 128 + 4 * lane]);

        float* base = &g_msum[(size_t)d * 256];
        red_add_v4(base + 4 * lane, hn4);
        red_add_v4(base + 128 + 4 * lane, he);
        if (lane == 0) red_add_u32(&g_deg[d], 1u);
    }
}

// ---------------------------------------------------------------------------
// K4: out = Wr @ (concat((hn+sum_n), sum_e) / (deg+1)) + br ; zero if deg==0
//     (tile: 32 nodes x 256 outputs per CTA)
// ---------------------------------------------------------------------------
__global__ __launch_bounds__(256) void node_kernel(const float* __restrict__ br,
                                                   float* __restrict__ out,
                                                   int n_nodes) {
    __shared__ float ts[32][256];
    __shared__ float inv_s[32];
    __shared__ unsigned degi_s[32];
    int node0 = blockIdx.x * 32;
    int tid = threadIdx.x;

    if (tid < 32) {
        int n = node0 + tid;
        unsigned dg = (n < n_nodes) ? g_deg[n] : 0u;
        degi_s[tid] = dg;
        inv_s[tid] = 1.0f / (float)(dg + 1u);
    }
    __syncthreads();

    for (int i = tid; i < 32 * 64; i += 256) {
        int n = i >> 6, c = i & 63;  // float4 column
        int gn = node0 + n;
        float4 v = make_float4(0.f, 0.f, 0.f, 0.f);
        if (gn < n_nodes) {
            float inv = inv_s[n];
            float4 m = reinterpret_cast<const float4*>(&g_msum[(size_t)gn * 256])[c];
            if (c < 32) {
                float4 h = reinterpret_cast<const float4*>(&g_hn[(size_t)gn * 128])[c];
                v = make_float4((h.x + m.x) * inv, (h.y + m.y) * inv,
                                (h.z + m.z) * inv, (h.w + m.w) * inv);
            } else {
                v = make_float4(m.x * inv, m.y * inv, m.z * inv, m.w * inv);
            }
        }
        *reinterpret_cast<float4*>(&ts[n][4 * c]) = v;
    }
    __syncthreads();

    int jq = tid & 63;   // output quad: j = 4*jq .. 4*jq+3 (256 outputs)
    int ng = tid >> 6;   // node group of 8

    float4 brv = *reinterpret_cast<const float4*>(&br[4 * jq]);
    float4 acc[8];
#pragma unroll
    for (int r = 0; r < 8; r++) acc[r] = brv;

#pragma unroll 2
    for (int k = 0; k < 256; k++) {
        float4 w = *reinterpret_cast<const float4*>(&g_WrT[(size_t)k * 256 + 4 * jq]);
#pragma unroll
        for (int r = 0; r < 8; r++) {
            float t = ts[ng * 8 + r][k];
            acc[r].x += w.x * t; acc[r].y += w.y * t;
            acc[r].z += w.z * t; acc[r].w += w.w * t;
        }
    }

#pragma unroll
    for (int r = 0; r < 8; r++) {
        int n = node0 + ng * 8 + r;
        if (n < n_nodes) {
            float4 o = acc[r];
            if (degi_s[ng * 8 + r] == 0u) o = make_float4(0.f, 0.f, 0.f, 0.f);
            *reinterpret_cast<float4*>(&out[(size_t)n * 256 + 4 * jq]) = o;
        }
    }
}

// ---------------------------------------------------------------------------
extern "C" void kernel_launch(void* const* d_in, const int* in_sizes, int n_in,
                              void* d_out, int out_size) {
    const float* x  = (const float*)d_in[0];
    const float* ez = (const float*)d_in[1];
    const int* src  = (const int*)d_in[2];
    const int* dst  = (const int*)d_in[3];
    const float* Wn = (const float*)d_in[4];
    const float* bn = (const float*)d_in[5];
    const float* We = (const float*)d_in[6];
    const float* be = (const float*)d_in[7];
    const float* Wr = (const float*)d_in[8];
    const float* br = (const float*)d_in[9];
    float* out = (float*)d_out;

    int n_nodes = in_sizes[0] / 256;
    int n_edges = in_sizes[2];

    zero_kernel<<<1024, 256>>>(n_nodes);
    prep_kernel<<<(128 * 256 + 256 * 256 + 255) / 256, 256>>>(Wn, Wr);
    hn_kernel<<<(n_nodes + 31) / 32, 256>>>(x, bn, n_nodes);
    edge_kernel<<<2048, 256>>>(ez, src, dst, We, be, n_edges);
    node_kernel<<<(n_nodes + 31) / 32, 256>>>(br, out, n_nodes);
}

// round 2
// speedup vs baseline: 4.3204x; 4.3204x over previous
#include <cuda_runtime.h>
#include <cstdint>

#define MAX_NODES 50048

// Scratch (static __device__ arrays — allocation-free per harness rules)
__device__ __align__(16) float    g_hn[(size_t)MAX_NODES * 128];   // node projections
__device__ __align__(16) float    g_msum[(size_t)MAX_NODES * 128]; // sum of hn[src] per dst
__device__ __align__(16) float    g_sez[(size_t)MAX_NODES * 64];   // sum of ez per dst
__device__ unsigned g_deg[MAX_NODES];
__device__ __align__(16) float    g_WnT[256 * 128];                // Wn^T  (k-major)
__device__ __align__(16) float    g_Wr1T[128 * 256];               // Wr[:, :128]^T (k-major)
__device__ __align__(16) float    g_WcT[64 * 256];                 // (Wr2 @ We)^T  (k-major)
__device__ __align__(16) float    g_vbe[256];                      // Wr2 @ be

__device__ __forceinline__ void red_add_v4(float* p, float4 v) {
    asm volatile("red.global.add.v4.f32 [%0], {%1,%2,%3,%4};"
                 :: "l"(p), "f"(v.x), "f"(v.y), "f"(v.z), "f"(v.w) : "memory");
}
__device__ __forceinline__ void red_add_u32(unsigned* p, unsigned v) {
    asm volatile("red.global.add.u32 [%0], %1;" :: "l"(p), "r"(v) : "memory");
}

// ---------------------------------------------------------------------------
// K0: zero accumulators
// ---------------------------------------------------------------------------
__global__ void zero_kernel(int n_nodes) {
    int stride = gridDim.x * blockDim.x;
    int tid = blockIdx.x * blockDim.x + threadIdx.x;
    float4 z = make_float4(0.f, 0.f, 0.f, 0.f);
    int t1 = n_nodes * 32;   // msum float4s
    for (int i = tid; i < t1; i += stride)
        reinterpret_cast<float4*>(g_msum)[i] = z;
    int t2 = n_nodes * 16;   // sez float4s
    for (int i = tid; i < t2; i += stride)
        reinterpret_cast<float4*>(g_sez)[i] = z;
    for (int i = tid; i < n_nodes; i += stride)
        g_deg[i] = 0u;
}

// ---------------------------------------------------------------------------
// K1a: transposes: Wn -> WnT, Wr[:, :128] -> Wr1T
// ---------------------------------------------------------------------------
__global__ void prep_kernel(const float* __restrict__ Wn, const float* __restrict__ Wr) {
    int i = blockIdx.x * blockDim.x + threadIdx.x;
    if (i < 128 * 256) {                 // Wn [128,256]
        int j = i >> 8, k = i & 255;
        g_WnT[k * 128 + j] = Wn[i];
    }
    int i2 = i - 128 * 256;
    if (i2 >= 0 && i2 < 256 * 128) {     // Wr1: j<256 rows, k<128 cols
        int j = i2 >> 7, k = i2 & 127;
        g_Wr1T[k * 256 + j] = Wr[j * 256 + k];
    }
}

// ---------------------------------------------------------------------------
// K1b: WcT[k][j] = sum_m Wr[j][128+m] * We[m][k]   (k<64, j<256)
//      vbe[j]    = sum_m Wr[j][128+m] * be[m]
//      one block per j, 64 threads (one per k)
// ---------------------------------------------------------------------------
__global__ __launch_bounds__(64) void wc_kernel(const float* __restrict__ Wr,
                                                const float* __restrict__ We,
                                                const float* __restrict__ be) {
    int j = blockIdx.x;
    int k = threadIdx.x;
    const float* wr2 = Wr + (size_t)j * 256 + 128;
    float acc = 0.f;
#pragma unroll 8
    for (int m = 0; m < 128; m++)
        acc += wr2[m] * We[(size_t)m * 64 + k];
    g_WcT[(size_t)k * 256 + j] = acc;

    __shared__ float red[64];
    red[k] = wr2[k] * be[k] + wr2[k + 64] * be[k + 64];
    __syncthreads();
#pragma unroll
    for (int s = 32; s > 0; s >>= 1) {
        if (k < s) red[k] += red[k + s];
        __syncthreads();
    }
    if (k == 0) g_vbe[j] = red[0];
}

// ---------------------------------------------------------------------------
// K2: hn = x @ Wn^T + bn     (tile: 32 nodes x 128 outputs per CTA)
// ---------------------------------------------------------------------------
__global__ __launch_bounds__(256) void hn_kernel(const float* __restrict__ x,
                                                 const float* __restrict__ bn,
                                                 int n_nodes) {
    __shared__ float xs[32][256];
    int node0 = blockIdx.x * 32;
    int tid = threadIdx.x;

    for (int i = tid; i < 32 * 64; i += 256) {
        int n = i >> 6, c = i & 63;
        float4 v = make_float4(0.f, 0.f, 0.f, 0.f);
        if (node0 + n < n_nodes)
            v = reinterpret_cast<const float4*>(x + (size_t)(node0 + n) * 256)[c];
        *reinterpret_cast<float4*>(&xs[n][4 * c]) = v;
    }
    __syncthreads();

    int jq = tid & 31;   // output quad: j = 4*jq .. 4*jq+3   (128 outputs)
    int ng = tid >> 5;   // node group of 4

    float4 bq = *reinterpret_cast<const float4*>(&bn[4 * jq]);
    float4 acc[4];
#pragma unroll
    for (int r = 0; r < 4; r++) acc[r] = bq;

#pragma unroll 4
    for (int k = 0; k < 256; k++) {
        float4 w = *reinterpret_cast<const float4*>(&g_WnT[(size_t)k * 128 + 4 * jq]);
#pragma unroll
        for (int r = 0; r < 4; r++) {
            float t = xs[ng * 4 + r][k];
            acc[r].x += w.x * t; acc[r].y += w.y * t;
            acc[r].z += w.z * t; acc[r].w += w.w * t;
        }
    }
#pragma unroll
    for (int r = 0; r < 4; r++) {
        int n = node0 + ng * 4 + r;
        if (n < n_nodes)
            *reinterpret_cast<float4*>(&g_hn[(size_t)n * 128 + 4 * jq]) = acc[r];
    }
}

// ---------------------------------------------------------------------------
// K3: edge scatter — one warp per edge, pure gather/RED (no math):
//     msum[dst] += hn[src];  sez[dst] += ez[e];  deg[dst] += 1
// ---------------------------------------------------------------------------
__global__ __launch_bounds__(256) void edge_kernel(const float* __restrict__ ez,
                                                   const int* __restrict__ src,
                                                   const int* __restrict__ dst,
                                                   int n_edges) {
    int lane = threadIdx.x & 31;
    int warp = blockIdx.x * (blockDim.x >> 5) + (threadIdx.x >> 5);
    int nwarps = gridDim.x * (blockDim.x >> 5);

#pragma unroll 2
    for (int e = warp; e < n_edges; e += nwarps) {
        int s = __ldg(&src[e]);
        int d = __ldg(&dst[e]);
        float4 ev = make_float4(0.f, 0.f, 0.f, 0.f);
        if (lane < 16)
            ev = reinterpret_cast<const float4*>(ez)[(size_t)e * 16 + lane];
        float4 hg = reinterpret_cast<const float4*>(g_hn)[(size_t)s * 32 + lane];

        red_add_v4(&g_msum[(size_t)d * 128 + 4 * lane], hg);
        if (lane < 16)
            red_add_v4(&g_sez[(size_t)d * 64 + 4 * lane], ev);
        if (lane == 0)
            red_add_u32(&g_deg[d], 1u);
    }
}

// ---------------------------------------------------------------------------
// K4: out = Wr1@((hn+msum)*inv) + Wc@(sez*inv) + (deg*inv)*vbe + br
//     zero if deg==0.   Tile: 32 nodes x 256 outputs per CTA.
// ---------------------------------------------------------------------------
__global__ __launch_bounds__(256) void node_kernel(const float* __restrict__ br,
                                                   float* __restrict__ out,
                                                   int n_nodes) {
    __shared__ float ts[32][192];      // [0:128)=s1, [128:192)=s2
    __shared__ float inv_s[32];
    __shared__ float dinv_s[32];
    __shared__ unsigned deg_s[32];
    int node0 = blockIdx.x * 32;
    int tid = threadIdx.x;

    if (tid < 32) {
        int n = node0 + tid;
        unsigned dg = (n < n_nodes) ? g_deg[n] : 0u;
        deg_s[tid] = dg;
        float inv = 1.0f / (float)(dg + 1u);
        inv_s[tid] = inv;
        dinv_s[tid] = (float)dg * inv;
    }
    __syncthreads();

    // stage states: 48 float4 per node (32 for s1, 16 for s2)
    for (int i = tid; i < 32 * 48; i += 256) {
        int n = i / 48, c = i % 48;
        int gn = node0 + n;
        float4 v = make_float4(0.f, 0.f, 0.f, 0.f);
        if (gn < n_nodes) {
            float inv = inv_s[n];
            if (c < 32) {
                float4 m = reinterpret_cast<const float4*>(&g_msum[(size_t)gn * 128])[c];
                float4 h = reinterpret_cast<const float4*>(&g_hn[(size_t)gn * 128])[c];
                v = make_float4((h.x + m.x) * inv, (h.y + m.y) * inv,
                                (h.z + m.z) * inv, (h.w + m.w) * inv);
            } else {
                float4 sv = reinterpret_cast<const float4*>(&g_sez[(size_t)gn * 64])[c - 32];
                v = make_float4(sv.x * inv, sv.y * inv, sv.z * inv, sv.w * inv);
            }
        }
        *reinterpret_cast<float4*>(&ts[n][4 * c]) = v;
    }
    __syncthreads();

    int jq = tid & 63;   // output quad (256 outputs)
    int ng = tid >> 6;   // node group of 8 (4 groups)

    float4 brv = *reinterpret_cast<const float4*>(&br[4 * jq]);
    float4 vb  = *reinterpret_cast<const float4*>(&g_vbe[4 * jq]);

    float4 acc[8];
#pragma unroll
    for (int r = 0; r < 8; r++) {
        float di = dinv_s[ng * 8 + r];
        acc[r] = make_float4(brv.x + di * vb.x, brv.y + di * vb.y,
                             brv.z + di * vb.z, brv.w + di * vb.w);
    }

#pragma unroll 2
    for (int k = 0; k < 128; k++) {
        float4 w = *reinterpret_cast<const float4*>(&g_Wr1T[(size_t)k * 256 + 4 * jq]);
#pragma unroll
        for (int r = 0; r < 8; r++) {
            float t = ts[ng * 8 + r][k];
            acc[r].x += w.x * t; acc[r].y += w.y * t;
            acc[r].z += w.z * t; acc[r].w += w.w * t;
        }
    }
#pragma unroll 2
    for (int k = 0; k < 64; k++) {
        float4 w = *reinterpret_cast<const float4*>(&g_WcT[(size_t)k * 256 + 4 * jq]);
#pragma unroll
        for (int r = 0; r < 8; r++) {
            float t = ts[ng * 8 + r][128 + k];
            acc[r].x += w.x * t; acc[r].y += w.y * t;
            acc[r].z += w.z * t; acc[r].w += w.w * t;
        }
    }

#pragma unroll
    for (int r = 0; r < 8; r++) {
        int n = node0 + ng * 8 + r;
        if (n < n_nodes) {
            float4 o = acc[r];
            if (deg_s[ng * 8 + r] == 0u) o = make_float4(0.f, 0.f, 0.f, 0.f);
            *reinterpret_cast<float4*>(&out[(size_t)n * 256 + 4 * jq]) = o;
        }
    }
}

// ---------------------------------------------------------------------------
extern "C" void kernel_launch(void* const* d_in, const int* in_sizes, int n_in,
                              void* d_out, int out_size) {
    const float* x  = (const float*)d_in[0];
    const float* ez = (const float*)d_in[1];
    const int* src  = (const int*)d_in[2];
    const int* dst  = (const int*)d_in[3];
    const float* Wn = (const float*)d_in[4];
    const float* bn = (const float*)d_in[5];
    const float* We = (const float*)d_in[6];
    const float* be = (const float*)d_in[7];
    const float* Wr = (const float*)d_in[8];
    const float* br = (const float*)d_in[9];
    float* out = (float*)d_out;

    int n_nodes = in_sizes[0] / 256;
    int n_edges = in_sizes[2];

    zero_kernel<<<1024, 256>>>(n_nodes);
    prep_kernel<<<(128 * 256 + 256 * 128 + 255) / 256, 256>>>(Wn, Wr);
    wc_kernel<<<256, 64>>>(Wr, We, be);
    hn_kernel<<<(n_nodes + 31) / 32, 256>>>(x, bn, n_nodes);
    edge_kernel<<<2048, 256>>>(ez, src, dst, n_edges);
    node_kernel<<<(n_nodes + 31) / 32, 256>>>(br, out, n_nodes);
}

// round 3
// speedup vs baseline: 4.4349x; 1.0265x over previous
#include <cuda_runtime.h>
#include <cstdint>

#define MAX_NODES 50048
#define MAX_EDGES 1600000

// Scratch (static __device__ arrays — allocation-free per harness rules)
__device__ __align__(16) float    g_hn[(size_t)MAX_NODES * 128];    // node projections
__device__ __align__(16) float    g_state[(size_t)MAX_NODES * 192]; // mean state (scaled)
__device__ float    g_dinv[MAX_NODES];                              // deg/(deg+1)
__device__ unsigned g_deg[MAX_NODES];
__device__ unsigned g_off[MAX_NODES];
__device__ unsigned g_cur[MAX_NODES];
__device__ __align__(16) int2     g_epair[MAX_EDGES];               // (src, edge_id) binned by dst
__device__ __align__(16) float    g_WnT[256 * 128];                 // Wn^T  (k-major)
__device__ __align__(16) float    g_Wr1T[128 * 256];                // Wr[:, :128]^T (k-major)
__device__ __align__(16) float    g_WcT[64 * 256];                  // (Wr2 @ We)^T  (k-major)
__device__ __align__(16) float    g_vbe[256];                       // Wr2 @ be

__device__ __forceinline__ void red_add_u32(unsigned* p, unsigned v) {
    asm volatile("red.global.add.u32 [%0], %1;" :: "l"(p), "r"(v) : "memory");
}

// ---------------------------------------------------------------------------
// K0: zero degree counters
// ---------------------------------------------------------------------------
__global__ void zero_kernel(int n_nodes) {
    int tid = blockIdx.x * blockDim.x + threadIdx.x;
    if (tid < n_nodes) g_deg[tid] = 0u;
}

// ---------------------------------------------------------------------------
// K1a: transposes: Wn -> WnT, Wr[:, :128] -> Wr1T
// ---------------------------------------------------------------------------
__global__ void prep_kernel(const float* __restrict__ Wn, const float* __restrict__ Wr) {
    int i = blockIdx.x * blockDim.x + threadIdx.x;
    if (i < 128 * 256) {                 // Wn [128,256]
        int j = i >> 8, k = i & 255;
        g_WnT[k * 128 + j] = Wn[i];
    }
    int i2 = i - 128 * 256;
    if (i2 >= 0 && i2 < 256 * 128) {     // Wr1: j<256 rows, k<128 cols
        int j = i2 >> 7, k = i2 & 127;
        g_Wr1T[k * 256 + j] = Wr[j * 256 + k];
    }
}

// ---------------------------------------------------------------------------
// K1b: WcT[k][j] = sum_m Wr[j][128+m] * We[m][k] ;  vbe[j] = Wr2[j]·be
// ---------------------------------------------------------------------------
__global__ __launch_bounds__(64) void wc_kernel(const float* __restrict__ Wr,
                                                const float* __restrict__ We,
                                                const float* __restrict__ be) {
    int j = blockIdx.x;
    int k = threadIdx.x;
    const float* wr2 = Wr + (size_t)j * 256 + 128;
    float acc = 0.f;
#pragma unroll 8
    for (int m = 0; m < 128; m++)
        acc += wr2[m] * We[(size_t)m * 64 + k];
    g_WcT[(size_t)k * 256 + j] = acc;

    __shared__ float red[64];
    red[k] = wr2[k] * be[k] + wr2[k + 64] * be[k + 64];
    __syncthreads();
#pragma unroll
    for (int s = 32; s > 0; s >>= 1) {
        if (k < s) red[k] += red[k + s];
        __syncthreads();
    }
    if (k == 0) g_vbe[j] = red[0];
}

// ---------------------------------------------------------------------------
// K2: hn = x @ Wn^T + bn    (tile: 32 nodes x 128 outs, 128 threads,
//      8 nodes per thread -> 32 FFMA per 12 LDS-wavefronts per k)
// ---------------------------------------------------------------------------
__global__ __launch_bounds__(128) void hn_kernel(const float* __restrict__ x,
                                                 const float* __restrict__ bn,
                                                 int n_nodes) {
    __shared__ float xs[32][256];
    int node0 = blockIdx.x * 32;
    int tid = threadIdx.x;

    for (int i = tid; i < 32 * 64; i += 128) {
        int n = i >> 6, c = i & 63;
        float4 v = make_float4(0.f, 0.f, 0.f, 0.f);
        if (node0 + n < n_nodes)
            v = reinterpret_cast<const float4*>(x + (size_t)(node0 + n) * 256)[c];
        *reinterpret_cast<float4*>(&xs[n][4 * c]) = v;
    }
    __syncthreads();

    int jq = tid & 31;   // output quad (128 outputs)
    int ng = tid >> 5;   // 4 groups x 8 nodes

    float4 bq = *reinterpret_cast<const float4*>(&bn[4 * jq]);
    float4 acc[8];
#pragma unroll
    for (int r = 0; r < 8; r++) acc[r] = bq;

#pragma unroll 4
    for (int k = 0; k < 256; k++) {
        float4 w = *reinterpret_cast<const float4*>(&g_WnT[(size_t)k * 128 + 4 * jq]);
#pragma unroll
        for (int r = 0; r < 8; r++) {
            float t = xs[ng * 8 + r][k];
            acc[r].x += w.x * t; acc[r].y += w.y * t;
            acc[r].z += w.z * t; acc[r].w += w.w * t;
        }
    }
#pragma unroll
    for (int r = 0; r < 8; r++) {
        int n = node0 + ng * 8 + r;
        if (n < n_nodes)
            *reinterpret_cast<float4*>(&g_hn[(size_t)n * 128 + 4 * jq]) = acc[r];
    }
}

// ---------------------------------------------------------------------------
// K3a: count in-degree
// ---------------------------------------------------------------------------
__global__ void count_kernel(const int* __restrict__ dst, int n_edges) {
    int stride = gridDim.x * blockDim.x;
    for (int e = blockIdx.x * blockDim.x + threadIdx.x; e < n_edges; e += stride)
        red_add_u32(&g_deg[__ldg(&dst[e])], 1u);
}

// ---------------------------------------------------------------------------
// K3b: exclusive scan of degrees -> g_off, g_cur  (single CTA, 1024 threads)
// ---------------------------------------------------------------------------
__global__ __launch_bounds__(1024) void scan_kernel(int n_nodes) {
    __shared__ unsigned part[1024];
    int t = threadIdx.x;
    int chunk = (n_nodes + 1023) >> 10;
    int lo = t * chunk;
    int hi = min(lo + chunk, n_nodes);

    unsigned s = 0;
    for (int i = lo; i < hi; i++) s += g_deg[i];
    part[t] = s;
    __syncthreads();
#pragma unroll
    for (int d = 1; d < 1024; d <<= 1) {
        unsigned v = (t >= d) ? part[t - d] : 0u;
        __syncthreads();
        part[t] += v;
        __syncthreads();
    }
    unsigned base = (t == 0) ? 0u : part[t - 1];
    for (int i = lo; i < hi; i++) {
        unsigned c = g_deg[i];
        g_off[i] = base;
        g_cur[i] = base;
        base += c;
    }
}

// ---------------------------------------------------------------------------
// K3c: bin edges by dst:  g_epair[pos] = (src, e)
// ---------------------------------------------------------------------------
__global__ void fill_kernel(const int* __restrict__ src, const int* __restrict__ dst,
                            int n_edges) {
    int stride = gridDim.x * blockDim.x;
    for (int e = blockIdx.x * blockDim.x + threadIdx.x; e < n_edges; e += stride) {
        int d = __ldg(&dst[e]);
        unsigned pos = atomicAdd(&g_cur[d], 1u);
        g_epair[pos] = make_int2(__ldg(&src[e]), e);
    }
}

// ---------------------------------------------------------------------------
// K3d: warp-per-node gather: registers accumulate sum(hn[src]) and sum(ez),
//      then write scaled mean-state (192 floats/node).
// ---------------------------------------------------------------------------
__global__ __launch_bounds__(256) void gather_kernel(const float* __restrict__ ez,
                                                     int n_nodes) {
    int lane = threadIdx.x & 31;
    int n = blockIdx.x * 8 + (threadIdx.x >> 5);
    if (n >= n_nodes) return;

    unsigned off = g_off[n];
    int deg = (int)g_deg[n];
    const int2* ep = g_epair + off;

    float4 ah = make_float4(0.f, 0.f, 0.f, 0.f);
    float2 ae = make_float2(0.f, 0.f);

    int i = 0;
    int d4 = deg & ~3;
    for (; i < d4; i += 4) {
        int2 p0 = __ldg(&ep[i + 0]);
        int2 p1 = __ldg(&ep[i + 1]);
        int2 p2 = __ldg(&ep[i + 2]);
        int2 p3 = __ldg(&ep[i + 3]);
        float4 h0 = *reinterpret_cast<const float4*>(&g_hn[(size_t)p0.x * 128 + 4 * lane]);
        float4 h1 = *reinterpret_cast<const float4*>(&g_hn[(size_t)p1.x * 128 + 4 * lane]);
        float4 h2 = *reinterpret_cast<const float4*>(&g_hn[(size_t)p2.x * 128 + 4 * lane]);
        float4 h3 = *reinterpret_cast<const float4*>(&g_hn[(size_t)p3.x * 128 + 4 * lane]);
        float2 e0 = *reinterpret_cast<const float2*>(&ez[(size_t)p0.y * 64 + 2 * lane]);
        float2 e1 = *reinterpret_cast<const float2*>(&ez[(size_t)p1.y * 64 + 2 * lane]);
        float2 e2 = *reinterpret_cast<const float2*>(&ez[(size_t)p2.y * 64 + 2 * lane]);
        float2 e3 = *reinterpret_cast<const float2*>(&ez[(size_t)p3.y * 64 + 2 * lane]);
        ah.x += h0.x + h1.x + h2.x + h3.x;
        ah.y += h0.y + h1.y + h2.y + h3.y;
        ah.z += h0.z + h1.z + h2.z + h3.z;
        ah.w += h0.w + h1.w + h2.w + h3.w;
        ae.x += e0.x + e1.x + e2.x + e3.x;
        ae.y += e0.y + e1.y + e2.y + e3.y;
    }
    for (; i < deg; i++) {
        int2 p = __ldg(&ep[i]);
        float4 h = *reinterpret_cast<const float4*>(&g_hn[(size_t)p.x * 128 + 4 * lane]);
        float2 ev = *reinterpret_cast<const float2*>(&ez[(size_t)p.y * 64 + 2 * lane]);
        ah.x += h.x; ah.y += h.y; ah.z += h.z; ah.w += h.w;
        ae.x += ev.x; ae.y += ev.y;
    }

    float inv = 1.0f / (float)(deg + 1);
    float4 selfh = *reinterpret_cast<const float4*>(&g_hn[(size_t)n * 128 + 4 * lane]);

    float* st = &g_state[(size_t)n * 192];
    float4 s1 = make_float4((selfh.x + ah.x) * inv, (selfh.y + ah.y) * inv,
                            (selfh.z + ah.z) * inv, (selfh.w + ah.w) * inv);
    *reinterpret_cast<float4*>(&st[4 * lane]) = s1;
    float2 s2 = make_float2(ae.x * inv, ae.y * inv);
    *reinterpret_cast<float2*>(&st[128 + 2 * lane]) = s2;
    if (lane == 0) g_dinv[n] = (float)deg * inv;
}

// ---------------------------------------------------------------------------
// K4: out = Wr1@s1 + Wc@s2 + dinv*vbe + br ; zero if deg==0
//     (tile: 32 nodes x 256 outs, 128 threads, 16 nodes per thread)
// ---------------------------------------------------------------------------
__global__ __launch_bounds__(128) void node_kernel(const float* __restrict__ br,
                                                   float* __restrict__ out,
                                                   int n_nodes) {
    __shared__ float ts[32][192];
    __shared__ float dinv_s[32];
    __shared__ unsigned deg_s[32];
    int node0 = blockIdx.x * 32;
    int tid = threadIdx.x;

    if (tid < 32) {
        int n = node0 + tid;
        deg_s[tid] = (n < n_nodes) ? g_deg[n] : 0u;
        dinv_s[tid] = (n < n_nodes) ? g_dinv[n] : 0.f;
    }

    for (int i = tid; i < 32 * 48; i += 128) {
        int n = i / 48, c = i % 48;
        int gn = node0 + n;
        float4 v = make_float4(0.f, 0.f, 0.f, 0.f);
        if (gn < n_nodes)
            v = reinterpret_cast<const float4*>(&g_state[(size_t)gn * 192])[c];
        *reinterpret_cast<float4*>(&ts[n][4 * c]) = v;
    }
    __syncthreads();

    int jq = tid & 63;   // output quad (256 outputs)
    int ng = tid >> 6;   // 2 groups x 16 nodes

    float4 brv = *reinterpret_cast<const float4*>(&br[4 * jq]);
    float4 vb  = *reinterpret_cast<const float4*>(&g_vbe[4 * jq]);

    float4 acc[16];
#pragma unroll
    for (int r = 0; r < 16; r++) {
        float di = dinv_s[ng * 16 + r];
        acc[r] = make_float4(brv.x + di * vb.x, brv.y + di * vb.y,
                             brv.z + di * vb.z, brv.w + di * vb.w);
    }

#pragma unroll 2
    for (int k = 0; k < 128; k++) {
        float4 w = *reinterpret_cast<const float4*>(&g_Wr1T[(size_t)k * 256 + 4 * jq]);
#pragma unroll
        for (int r = 0; r < 16; r++) {
            float t = ts[ng * 16 + r][k];
            acc[r].x += w.x * t; acc[r].y += w.y * t;
            acc[r].z += w.z * t; acc[r].w += w.w * t;
        }
    }
#pragma unroll 2
    for (int k = 0; k < 64; k++) {
        float4 w = *reinterpret_cast<const float4*>(&g_WcT[(size_t)k * 256 + 4 * jq]);
#pragma unroll
        for (int r = 0; r < 16; r++) {
            float t = ts[ng * 16 + r][128 + k];
            acc[r].x += w.x * t; acc[r].y += w.y * t;
            acc[r].z += w.z * t; acc[r].w += w.w * t;
        }
    }

#pragma unroll
    for (int r = 0; r < 16; r++) {
        int n = node0 + ng * 16 + r;
        if (n < n_nodes) {
            float4 o = acc[r];
            if (deg_s[ng * 16 + r] == 0u) o = make_float4(0.f, 0.f, 0.f, 0.f);
            *reinterpret_cast<float4*>(&out[(size_t)n * 256 + 4 * jq]) = o;
        }
    }
}

// ---------------------------------------------------------------------------
extern "C" void kernel_launch(void* const* d_in, const int* in_sizes, int n_in,
                              void* d_out, int out_size) {
    const float* x  = (const float*)d_in[0];
    const float* ez = (const float*)d_in[1];
    const int* src  = (const int*)d_in[2];
    const int* dst  = (const int*)d_in[3];
    const float* Wn = (const float*)d_in[4];
    const float* bn = (const float*)d_in[5];
    const float* We = (const float*)d_in[6];
    const float* be = (const float*)d_in[7];
    const float* Wr = (const float*)d_in[8];
    const float* br = (const float*)d_in[9];
    float* out = (float*)d_out;

    int n_nodes = in_sizes[0] / 256;
    int n_edges = in_sizes[2];

    zero_kernel<<<(n_nodes + 255) / 256, 256>>>(n_nodes);
    prep_kernel<<<(128 * 256 + 256 * 128 + 255) / 256, 256>>>(Wn, Wr);
    wc_kernel<<<256, 64>>>(Wr, We, be);
    count_kernel<<<1024, 256>>>(dst, n_edges);
    scan_kernel<<<1, 1024>>>(n_nodes);
    fill_kernel<<<1024, 256>>>(src, dst, n_edges);
    hn_kernel<<<(n_nodes + 31) / 32, 128>>>(x, bn, n_nodes);
    gather_kernel<<<(n_nodes + 7) / 8, 256>>>(ez, n_nodes);
    node_kernel<<<(n_nodes + 31) / 32, 128>>>(br, out, n_nodes);
}

// round 4
// speedup vs baseline: 4.9862x; 1.1243x over previous
#include <cuda_runtime.h>
#include <cstdint>

#define MAX_NODES 50048
#define MAX_EDGES 1600000

// Scratch (static __device__ arrays — allocation-free per harness rules)
__device__ __align__(16) float    g_hn[(size_t)MAX_NODES * 128];    // node projections
__device__ __align__(16) float    g_state[(size_t)MAX_NODES * 192]; // mean state (scaled)
__device__ float    g_dinv[MAX_NODES];                              // deg/(deg+1)
__device__ unsigned g_deg[MAX_NODES];
__device__ unsigned g_off[MAX_NODES];
__device__ unsigned g_cur[MAX_NODES];
__device__ __align__(16) int2     g_epair[MAX_EDGES];               // (src, edge_id) by dst
__device__ __align__(16) float    g_WnT[256 * 128];                 // Wn^T  (k-major)
__device__ __align__(16) float    g_Wr1T[128 * 256];                // Wr[:, :128]^T (k-major)
__device__ __align__(16) float    g_WcT[64 * 256];                  // (Wr2 @ We)^T  (k-major)
__device__ __align__(16) float    g_vbe[256];                       // Wr2 @ be

__device__ __forceinline__ void red_add_u32(unsigned* p, unsigned v) {
    asm volatile("red.global.add.u32 [%0], %1;" :: "l"(p), "r"(v) : "memory");
}
__device__ __forceinline__ uint64_t dup_f32x2(float a) {
    uint64_t r; asm("mov.b64 %0, {%1, %1};" : "=l"(r) : "f"(a)); return r;
}
__device__ __forceinline__ uint64_t pack_f32x2(float lo, float hi) {
    uint64_t r; asm("mov.b64 %0, {%1, %2};" : "=l"(r) : "f"(lo), "f"(hi)); return r;
}
__device__ __forceinline__ void ffma2(uint64_t& d, uint64_t a, uint64_t b) {
    asm("fma.rn.f32x2 %0, %1, %2, %0;" : "+l"(d) : "l"(a), "l"(b));
}
__device__ __forceinline__ float2 unpack_f32x2(uint64_t v) {
    float2 f; asm("mov.b64 {%0, %1}, %2;" : "=f"(f.x), "=f"(f.y) : "l"(v)); return f;
}

// ---------------------------------------------------------------------------
// K0: init — zero deg, transpose Wn -> WnT and Wr[:, :128] -> Wr1T
// ---------------------------------------------------------------------------
__global__ void init_kernel(const float* __restrict__ Wn, const float* __restrict__ Wr,
                            int n_nodes) {
    int i = blockIdx.x * blockDim.x + threadIdx.x;
    if (i < 128 * 256) {                 // Wn [128,256]
        int j = i >> 8, k = i & 255;
        g_WnT[k * 128 + j] = Wn[i];
    }
    if (i < 256 * 128) {                 // Wr1: j<256 rows, k<128 cols
        int j = i >> 7, k = i & 127;
        g_Wr1T[k * 256 + j] = Wr[j * 256 + k];
    }
    if (i < n_nodes) g_deg[i] = 0u;
}

// ---------------------------------------------------------------------------
// K1: WcT[k][j] = sum_m Wr[j][128+m] * We[m][k] ;  vbe[j] = Wr2[j]·be
// ---------------------------------------------------------------------------
__global__ __launch_bounds__(64) void wc_kernel(const float* __restrict__ Wr,
                                                const float* __restrict__ We,
                                                const float* __restrict__ be) {
    int j = blockIdx.x;
    int k = threadIdx.x;
    const float* wr2 = Wr + (size_t)j * 256 + 128;
    float acc = 0.f;
#pragma unroll 8
    for (int m = 0; m < 128; m++)
        acc += wr2[m] * We[(size_t)m * 64 + k];
    g_WcT[(size_t)k * 256 + j] = acc;

    __shared__ float red[64];
    red[k] = wr2[k] * be[k] + wr2[k + 64] * be[k + 64];
    __syncthreads();
#pragma unroll
    for (int s = 32; s > 0; s >>= 1) {
        if (k < s) red[k] += red[k + s];
        __syncthreads();
    }
    if (k == 0) g_vbe[j] = red[0];
}

// ---------------------------------------------------------------------------
// K2: fused   (a) hn = x @ Wn^T + bn  (f32x2 packed, 32 nodes x 128 outs/CTA)
//             (b) count in-degree (extra blocks)
// ---------------------------------------------------------------------------
__global__ __launch_bounds__(128) void hn_count_kernel(const float* __restrict__ x,
                                                       const float* __restrict__ bn,
                                                       const int* __restrict__ dst,
                                                       int n_nodes, int n_edges,
                                                       int hn_blocks) {
    __shared__ __align__(16) float xs[256][34];   // transposed [k][node], even pad
    int tid = threadIdx.x;

    if (blockIdx.x >= hn_blocks) {
        // ---- count part ----
        int cb = blockIdx.x - hn_blocks;
        int nthr = (gridDim.x - hn_blocks) * 128;
        for (int e = cb * 128 + tid; e < n_edges; e += nthr)
            red_add_u32(&g_deg[__ldg(&dst[e])], 1u);
        return;
    }

    int node0 = blockIdx.x * 32;

    // stage x tile transposed
    for (int i = tid; i < 32 * 64; i += 128) {
        int n = i >> 6, c = i & 63;
        float4 v = make_float4(0.f, 0.f, 0.f, 0.f);
        if (node0 + n < n_nodes)
            v = reinterpret_cast<const float4*>(x + (size_t)(node0 + n) * 256)[c];
        xs[4 * c + 0][n] = v.x;
        xs[4 * c + 1][n] = v.y;
        xs[4 * c + 2][n] = v.z;
        xs[4 * c + 3][n] = v.w;
    }
    __syncthreads();

    int jq = tid & 31;   // output quad (128 outputs)
    int ng = tid >> 5;   // 4 groups x 8 nodes (4 pairs)

    float4 bq = *reinterpret_cast<const float4*>(&bn[4 * jq]);
    uint64_t acc[4][4];  // [pair][out]
#pragma unroll
    for (int p = 0; p < 4; p++) {
        acc[p][0] = dup_f32x2(bq.x); acc[p][1] = dup_f32x2(bq.y);
        acc[p][2] = dup_f32x2(bq.z); acc[p][3] = dup_f32x2(bq.w);
    }

#pragma unroll 4
    for (int k = 0; k < 256; k++) {
        float4 w = *reinterpret_cast<const float4*>(&g_WnT[(size_t)k * 128 + 4 * jq]);
        uint64_t wx = dup_f32x2(w.x), wy = dup_f32x2(w.y),
                 wz = dup_f32x2(w.z), ww = dup_f32x2(w.w);
#pragma unroll
        for (int p = 0; p < 4; p++) {
            uint64_t t2 = *reinterpret_cast<const uint64_t*>(&xs[k][ng * 8 + 2 * p]);
            ffma2(acc[p][0], wx, t2);
            ffma2(acc[p][1], wy, t2);
            ffma2(acc[p][2], wz, t2);
            ffma2(acc[p][3], ww, t2);
        }
    }

#pragma unroll
    for (int p = 0; p < 4; p++) {
        float2 o0 = unpack_f32x2(acc[p][0]);
        float2 o1 = unpack_f32x2(acc[p][1]);
        float2 o2 = unpack_f32x2(acc[p][2]);
        float2 o3 = unpack_f32x2(acc[p][3]);
        int n = node0 + ng * 8 + 2 * p;
        if (n < n_nodes)
            *reinterpret_cast<float4*>(&g_hn[(size_t)n * 128 + 4 * jq]) =
                make_float4(o0.x, o1.x, o2.x, o3.x);
        if (n + 1 < n_nodes)
            *reinterpret_cast<float4*>(&g_hn[(size_t)(n + 1) * 128 + 4 * jq]) =
                make_float4(o0.y, o1.y, o2.y, o3.y);
    }
}

// ---------------------------------------------------------------------------
// K3: exclusive scan of degrees -> g_off, g_cur  (single CTA, 1024 threads)
// ---------------------------------------------------------------------------
__global__ __launch_bounds__(1024) void scan_kernel(int n_nodes) {
    __shared__ unsigned part[1024];
    int t = threadIdx.x;
    int chunk = (n_nodes + 1023) >> 10;
    int lo = t * chunk;
    int hi = min(lo + chunk, n_nodes);

    unsigned s = 0;
    for (int i = lo; i < hi; i++) s += g_deg[i];
    part[t] = s;
    __syncthreads();
#pragma unroll
    for (int d = 1; d < 1024; d <<= 1) {
        unsigned v = (t >= d) ? part[t - d] : 0u;
        __syncthreads();
        part[t] += v;
        __syncthreads();
    }
    unsigned base = (t == 0) ? 0u : part[t - 1];
    for (int i = lo; i < hi; i++) {
        unsigned c = g_deg[i];
        g_off[i] = base;
        g_cur[i] = base;
        base += c;
    }
}

// ---------------------------------------------------------------------------
// K4: bin edges by dst:  g_epair[pos] = (src, e)
// ---------------------------------------------------------------------------
__global__ void fill_kernel(const int* __restrict__ src, const int* __restrict__ dst,
                            int n_edges) {
    int stride = gridDim.x * blockDim.x;
    for (int e = blockIdx.x * blockDim.x + threadIdx.x; e < n_edges; e += stride) {
        int d = __ldg(&dst[e]);
        unsigned pos = atomicAdd(&g_cur[d], 1u);
        g_epair[pos] = make_int2(__ldg(&src[e]), e);
    }
}

// ---------------------------------------------------------------------------
// K5: warp-per-node gather: registers accumulate sum(hn[src]) and sum(ez),
//     write scaled mean-state (192 floats/node).
// ---------------------------------------------------------------------------
__global__ __launch_bounds__(256) void gather_kernel(const float* __restrict__ ez,
                                                     int n_nodes) {
    int lane = threadIdx.x & 31;
    int n = blockIdx.x * 8 + (threadIdx.x >> 5);
    if (n >= n_nodes) return;

    unsigned off = g_off[n];
    int deg = (int)g_deg[n];
    const int2* ep = g_epair + off;

    float4 ah = make_float4(0.f, 0.f, 0.f, 0.f);
    float2 ae = make_float2(0.f, 0.f);

    int i = 0;
    int d4 = deg & ~3;
    for (; i < d4; i += 4) {
        int2 p0 = __ldg(&ep[i + 0]);
        int2 p1 = __ldg(&ep[i + 1]);
        int2 p2 = __ldg(&ep[i + 2]);
        int2 p3 = __ldg(&ep[i + 3]);
        float4 h0 = *reinterpret_cast<const float4*>(&g_hn[(size_t)p0.x * 128 + 4 * lane]);
        float4 h1 = *reinterpret_cast<const float4*>(&g_hn[(size_t)p1.x * 128 + 4 * lane]);
        float4 h2 = *reinterpret_cast<const float4*>(&g_hn[(size_t)p2.x * 128 + 4 * lane]);
        float4 h3 = *reinterpret_cast<const float4*>(&g_hn[(size_t)p3.x * 128 + 4 * lane]);
        float2 e0 = *reinterpret_cast<const float2*>(&ez[(size_t)p0.y * 64 + 2 * lane]);
        float2 e1 = *reinterpret_cast<const float2*>(&ez[(size_t)p1.y * 64 + 2 * lane]);
        float2 e2 = *reinterpret_cast<const float2*>(&ez[(size_t)p2.y * 64 + 2 * lane]);
        float2 e3 = *reinterpret_cast<const float2*>(&ez[(size_t)p3.y * 64 + 2 * lane]);
        ah.x += h0.x + h1.x + h2.x + h3.x;
        ah.y += h0.y + h1.y + h2.y + h3.y;
        ah.z += h0.z + h1.z + h2.z + h3.z;
        ah.w += h0.w + h1.w + h2.w + h3.w;
        ae.x += e0.x + e1.x + e2.x + e3.x;
        ae.y += e0.y + e1.y + e2.y + e3.y;
    }
    for (; i < deg; i++) {
        int2 p = __ldg(&ep[i]);
        float4 h = *reinterpret_cast<const float4*>(&g_hn[(size_t)p.x * 128 + 4 * lane]);
        float2 ev = *reinterpret_cast<const float2*>(&ez[(size_t)p.y * 64 + 2 * lane]);
        ah.x += h.x; ah.y += h.y; ah.z += h.z; ah.w += h.w;
        ae.x += ev.x; ae.y += ev.y;
    }

    float inv = 1.0f / (float)(deg + 1);
    float4 selfh = *reinterpret_cast<const float4*>(&g_hn[(size_t)n * 128 + 4 * lane]);

    float* st = &g_state[(size_t)n * 192];
    *reinterpret_cast<float4*>(&st[4 * lane]) =
        make_float4((selfh.x + ah.x) * inv, (selfh.y + ah.y) * inv,
                    (selfh.z + ah.z) * inv, (selfh.w + ah.w) * inv);
    *reinterpret_cast<float2*>(&st[128 + 2 * lane]) = make_float2(ae.x * inv, ae.y * inv);
    if (lane == 0) g_dinv[n] = (float)deg * inv;
}

// ---------------------------------------------------------------------------
// K6: out = Wr1@s1 + Wc@s2 + dinv*vbe + br ; zero if deg==0
//     (f32x2 packed, 32 nodes x 256 outs per CTA, 128 threads)
// ---------------------------------------------------------------------------
__global__ __launch_bounds__(128) void node_kernel(const float* __restrict__ br,
                                                   float* __restrict__ out,
                                                   int n_nodes) {
    __shared__ __align__(16) float ts[192][34];   // transposed [k][node]
    __shared__ float dinv_s[32];
    __shared__ unsigned deg_s[32];
    int node0 = blockIdx.x * 32;
    int tid = threadIdx.x;

    if (tid < 32) {
        int n = node0 + tid;
        deg_s[tid] = (n < n_nodes) ? g_deg[n] : 0u;
        dinv_s[tid] = (n < n_nodes) ? g_dinv[n] : 0.f;
    }

    for (int i = tid; i < 32 * 48; i += 128) {
        int n = i / 48, c = i % 48;
        int gn = node0 + n;
        float4 v = make_float4(0.f, 0.f, 0.f, 0.f);
        if (gn < n_nodes)
            v = reinterpret_cast<const float4*>(&g_state[(size_t)gn * 192])[c];
        ts[4 * c + 0][n] = v.x;
        ts[4 * c + 1][n] = v.y;
        ts[4 * c + 2][n] = v.z;
        ts[4 * c + 3][n] = v.w;
    }
    __syncthreads();

    int jq = tid & 63;   // output quad (256 outputs)
    int ng = tid >> 6;   // 2 groups x 16 nodes (8 pairs)

    float4 brv = *reinterpret_cast<const float4*>(&br[4 * jq]);
    float4 vb  = *reinterpret_cast<const float4*>(&g_vbe[4 * jq]);

    uint64_t acc[8][4];  // [pair][out]
#pragma unroll
    for (int p = 0; p < 8; p++) {
        float d0 = dinv_s[ng * 16 + 2 * p];
        float d1 = dinv_s[ng * 16 + 2 * p + 1];
        acc[p][0] = pack_f32x2(brv.x + d0 * vb.x, brv.x + d1 * vb.x);
        acc[p][1] = pack_f32x2(brv.y + d0 * vb.y, brv.y + d1 * vb.y);
        acc[p][2] = pack_f32x2(brv.z + d0 * vb.z, brv.z + d1 * vb.z);
        acc[p][3] = pack_f32x2(brv.w + d0 * vb.w, brv.w + d1 * vb.w);
    }

#pragma unroll 2
    for (int k = 0; k < 128; k++) {
        float4 w = *reinterpret_cast<const float4*>(&g_Wr1T[(size_t)k * 256 + 4 * jq]);
        uint64_t wx = dup_f32x2(w.x), wy = dup_f32x2(w.y),
                 wz = dup_f32x2(w.z), ww = dup_f32x2(w.w);
#pragma unroll
        for (int p = 0; p < 8; p++) {
            uint64_t t2 = *reinterpret_cast<const uint64_t*>(&ts[k][ng * 16 + 2 * p]);
            ffma2(acc[p][0], wx, t2);
            ffma2(acc[p][1], wy, t2);
            ffma2(acc[p][2], wz, t2);
            ffma2(acc[p][3], ww, t2);
        }
    }
#pragma unroll 2
    for (int k = 0; k < 64; k++) {
        float4 w = *reinterpret_cast<const float4*>(&g_WcT[(size_t)k * 256 + 4 * jq]);
        uint64_t wx = dup_f32x2(w.x), wy = dup_f32x2(w.y),
                 wz = dup_f32x2(w.z), ww = dup_f32x2(w.w);
#pragma unroll
        for (int p = 0; p < 8; p++) {
            uint64_t t2 = *reinterpret_cast<const uint64_t*>(&ts[128 + k][ng * 16 + 2 * p]);
            ffma2(acc[p][0], wx, t2);
            ffma2(acc[p][1], wy, t2);
            ffma2(acc[p][2], wz, t2);
            ffma2(acc[p][3], ww, t2);
        }
    }

#pragma unroll
    for (int p = 0; p < 8; p++) {
        float2 o0 = unpack_f32x2(acc[p][0]);
        float2 o1 = unpack_f32x2(acc[p][1]);
        float2 o2 = unpack_f32x2(acc[p][2]);
        float2 o3 = unpack_f32x2(acc[p][3]);
        int n = node0 + ng * 16 + 2 * p;
        if (n < n_nodes) {
            float4 o = make_float4(o0.x, o1.x, o2.x, o3.x);
            if (deg_s[ng * 16 + 2 * p] == 0u) o = make_float4(0.f, 0.f, 0.f, 0.f);
            *reinterpret_cast<float4*>(&out[(size_t)n * 256 + 4 * jq]) = o;
        }
        if (n + 1 < n_nodes) {
            float4 o = make_float4(o0.y, o1.y, o2.y, o3.y);
            if (deg_s[ng * 16 + 2 * p + 1] == 0u) o = make_float4(0.f, 0.f, 0.f, 0.f);
            *reinterpret_cast<float4*>(&out[(size_t)(n + 1) * 256 + 4 * jq]) = o;
        }
    }
}

// ---------------------------------------------------------------------------
extern "C" void kernel_launch(void* const* d_in, const int* in_sizes, int n_in,
                              void* d_out, int out_size) {
    const float* x  = (const float*)d_in[0];
    const float* ez = (const float*)d_in[1];
    const int* src  = (const int*)d_in[2];
    const int* dst  = (const int*)d_in[3];
    const float* Wn = (const float*)d_in[4];
    const float* bn = (const float*)d_in[5];
    const float* We = (const float*)d_in[6];
    const float* be = (const float*)d_in[7];
    const float* Wr = (const float*)d_in[8];
    const float* br = (const float*)d_in[9];
    float* out = (float*)d_out;

    int n_nodes = in_sizes[0] / 256;
    int n_edges = in_sizes[2];

    int init_elems = (n_nodes > 128 * 256) ? n_nodes : 128 * 256;
    init_kernel<<<(init_elems + 255) / 256, 256>>>(Wn, Wr, n_nodes);
    wc_kernel<<<256, 64>>>(Wr, We, be);

    int hn_blocks = (n_nodes + 31) / 32;
    hn_count_kernel<<<hn_blocks + 256, 128>>>(x, bn, dst, n_nodes, n_edges, hn_blocks);

    scan_kernel<<<1, 1024>>>(n_nodes);
    fill_kernel<<<1024, 256>>>(src, dst, n_edges);
    gather_kernel<<<(n_nodes + 7) / 8, 256>>>(ez, n_nodes);
    node_kernel<<<(n_nodes + 31) / 32, 128>>>(br, out, n_nodes);
}

// round 5
// speedup vs baseline: 5.9147x; 1.1862x over previous
#include <cuda_runtime.h>
#include <cstdint>

#define MAX_NODES 50048
#define MAX_EDGES 1600000

// Scratch (static __device__ arrays — allocation-free per harness rules)
__device__ __align__(16) float    g_hn[(size_t)MAX_NODES * 128];    // node projections
__device__ __align__(16) float    g_state[(size_t)MAX_NODES * 192]; // mean state (scaled)
__device__ float    g_dinv[MAX_NODES];                              // deg/(deg+1)
__device__ unsigned g_deg[MAX_NODES];
__device__ unsigned g_off[MAX_NODES];
__device__ unsigned g_cur[MAX_NODES];
__device__ unsigned g_total;
__device__ __align__(16) int2     g_epair[MAX_EDGES];               // (src, edge_id) by dst
__device__ __align__(16) float    g_WnT[256 * 128];                 // Wn^T  (k-major)
__device__ __align__(16) float    g_Wr1T[128 * 256];                // Wr[:, :128]^T (k-major)
__device__ __align__(16) float    g_WcT[64 * 256];                  // (Wr2 @ We)^T  (k-major)
__device__ __align__(16) float    g_vbe[256];                       // Wr2 @ be

__device__ __forceinline__ void red_add_u32(unsigned* p, unsigned v) {
    asm volatile("red.global.add.u32 [%0], %1;" :: "l"(p), "r"(v) : "memory");
}
__device__ __forceinline__ uint64_t dup_f32x2(float a) {
    uint64_t r; asm("mov.b64 %0, {%1, %1};" : "=l"(r) : "f"(a)); return r;
}
__device__ __forceinline__ uint64_t pack_f32x2(float lo, float hi) {
    uint64_t r; asm("mov.b64 %0, {%1, %2};" : "=l"(r) : "f"(lo), "f"(hi)); return r;
}
__device__ __forceinline__ void ffma2(uint64_t& d, uint64_t a, uint64_t b) {
    asm("fma.rn.f32x2 %0, %1, %2, %0;" : "+l"(d) : "l"(a), "l"(b));
}
__device__ __forceinline__ float2 unpack_f32x2(uint64_t v) {
    float2 f; asm("mov.b64 {%0, %1}, %2;" : "=f"(f.x), "=f"(f.y) : "l"(v)); return f;
}

// ---------------------------------------------------------------------------
// K0: init — zero deg/g_total, transpose Wn -> WnT and Wr[:, :128] -> Wr1T
// ---------------------------------------------------------------------------
__global__ void init_kernel(const float* __restrict__ Wn, const float* __restrict__ Wr,
                            int n_nodes) {
    int i = blockIdx.x * blockDim.x + threadIdx.x;
    if (i == 0) g_total = 0u;
    if (i < 128 * 256) {                 // Wn [128,256]
        int j = i >> 8, k = i & 255;
        g_WnT[k * 128 + j] = Wn[i];
    }
    if (i < 256 * 128) {                 // Wr1: j<256 rows, k<128 cols
        int j = i >> 7, k = i & 127;
        g_Wr1T[k * 256 + j] = Wr[j * 256 + k];
    }
    if (i < n_nodes) g_deg[i] = 0u;
}

// ---------------------------------------------------------------------------
// K1: WcT[k][j] = sum_m Wr[j][128+m] * We[m][k] ;  vbe[j] = Wr2[j]·be
// ---------------------------------------------------------------------------
__global__ __launch_bounds__(64) void wc_kernel(const float* __restrict__ Wr,
                                                const float* __restrict__ We,
                                                const float* __restrict__ be) {
    int j = blockIdx.x;
    int k = threadIdx.x;
    const float* wr2 = Wr + (size_t)j * 256 + 128;
    float acc = 0.f;
#pragma unroll 8
    for (int m = 0; m < 128; m++)
        acc += wr2[m] * We[(size_t)m * 64 + k];
    g_WcT[(size_t)k * 256 + j] = acc;

    __shared__ float red[64];
    red[k] = wr2[k] * be[k] + wr2[k + 64] * be[k + 64];
    __syncthreads();
#pragma unroll
    for (int s = 32; s > 0; s >>= 1) {
        if (k < s) red[k] += red[k + s];
        __syncthreads();
    }
    if (k == 0) g_vbe[j] = red[0];
}

// ---------------------------------------------------------------------------
// K2: fused   (a) hn = x @ Wn^T + bn  (f32x2 packed, 32 nodes x 128 outs/CTA)
//             (b) count in-degree (extra blocks)
// ---------------------------------------------------------------------------
__global__ __launch_bounds__(128) void hn_count_kernel(const float* __restrict__ x,
                                                       const float* __restrict__ bn,
                                                       const int* __restrict__ dst,
                                                       int n_nodes, int n_edges,
                                                       int hn_blocks) {
    __shared__ __align__(16) float xs[256][34];   // transposed [k][node], even pad
    int tid = threadIdx.x;

    if (blockIdx.x >= hn_blocks) {
        // ---- count part ----
        int cb = blockIdx.x - hn_blocks;
        int nthr = (gridDim.x - hn_blocks) * 128;
        for (int e = cb * 128 + tid; e < n_edges; e += nthr)
            red_add_u32(&g_deg[__ldg(&dst[e])], 1u);
        return;
    }

    int node0 = blockIdx.x * 32;

    // stage x tile transposed
    for (int i = tid; i < 32 * 64; i += 128) {
        int n = i >> 6, c = i & 63;
        float4 v = make_float4(0.f, 0.f, 0.f, 0.f);
        if (node0 + n < n_nodes)
            v = reinterpret_cast<const float4*>(x + (size_t)(node0 + n) * 256)[c];
        xs[4 * c + 0][n] = v.x;
        xs[4 * c + 1][n] = v.y;
        xs[4 * c + 2][n] = v.z;
        xs[4 * c + 3][n] = v.w;
    }
    __syncthreads();

    int jq = tid & 31;   // output quad (128 outputs)
    int ng = tid >> 5;   // 4 groups x 8 nodes (4 pairs)

    float4 bq = *reinterpret_cast<const float4*>(&bn[4 * jq]);
    uint64_t acc[4][4];  // [pair][out]
#pragma unroll
    for (int p = 0; p < 4; p++) {
        acc[p][0] = dup_f32x2(bq.x); acc[p][1] = dup_f32x2(bq.y);
        acc[p][2] = dup_f32x2(bq.z); acc[p][3] = dup_f32x2(bq.w);
    }

#pragma unroll 4
    for (int k = 0; k < 256; k++) {
        float4 w = *reinterpret_cast<const float4*>(&g_WnT[(size_t)k * 128 + 4 * jq]);
        uint64_t wx = dup_f32x2(w.x), wy = dup_f32x2(w.y),
                 wz = dup_f32x2(w.z), ww = dup_f32x2(w.w);
#pragma unroll
        for (int p = 0; p < 4; p++) {
            uint64_t t2 = *reinterpret_cast<const uint64_t*>(&xs[k][ng * 8 + 2 * p]);
            ffma2(acc[p][0], wx, t2);
            ffma2(acc[p][1], wy, t2);
            ffma2(acc[p][2], wz, t2);
            ffma2(acc[p][3], ww, t2);
        }
    }

#pragma unroll
    for (int p = 0; p < 4; p++) {
        float2 o0 = unpack_f32x2(acc[p][0]);
        float2 o1 = unpack_f32x2(acc[p][1]);
        float2 o2 = unpack_f32x2(acc[p][2]);
        float2 o3 = unpack_f32x2(acc[p][3]);
        int n = node0 + ng * 8 + 2 * p;
        if (n < n_nodes)
            *reinterpret_cast<float4*>(&g_hn[(size_t)n * 128 + 4 * jq]) =
                make_float4(o0.x, o1.x, o2.x, o3.x);
        if (n + 1 < n_nodes)
            *reinterpret_cast<float4*>(&g_hn[(size_t)(n + 1) * 128 + 4 * jq]) =
                make_float4(o0.y, o1.y, o2.y, o3.y);
    }
}

// ---------------------------------------------------------------------------
// K3: parallel offset allocator (replaces serial scan) — segment order across
//     nodes is irrelevant for binning; only contiguity per node matters.
//     Warp-scan of degrees + one atomicAdd per warp on g_total.
// ---------------------------------------------------------------------------
__global__ __launch_bounds__(256) void alloc_kernel(int n_nodes) {
    int i = blockIdx.x * blockDim.x + threadIdx.x;
    int lane = threadIdx.x & 31;
    unsigned d = (i < n_nodes) ? g_deg[i] : 0u;

    unsigned s = d;
#pragma unroll
    for (int o = 1; o < 32; o <<= 1) {
        unsigned v = __shfl_up_sync(0xffffffffu, s, o);
        if (lane >= o) s += v;
    }
    unsigned warptot = __shfl_sync(0xffffffffu, s, 31);
    unsigned base = 0;
    if (lane == 31 && warptot > 0) base = atomicAdd(&g_total, warptot);
    base = __shfl_sync(0xffffffffu, base, 31);

    if (i < n_nodes) {
        unsigned off = base + s - d;
        g_off[i] = off;
        g_cur[i] = off;
    }
}

// ---------------------------------------------------------------------------
// K4: bin edges by dst:  g_epair[pos] = (src, e)
// ---------------------------------------------------------------------------
__global__ void fill_kernel(const int* __restrict__ src, const int* __restrict__ dst,
                            int n_edges) {
    int stride = gridDim.x * blockDim.x;
    for (int e = blockIdx.x * blockDim.x + threadIdx.x; e < n_edges; e += stride) {
        int d = __ldg(&dst[e]);
        unsigned pos = atomicAdd(&g_cur[d], 1u);
        g_epair[pos] = make_int2(__ldg(&src[e]), e);
    }
}

// ---------------------------------------------------------------------------
// K5: warp-per-node gather: registers accumulate sum(hn[src]) and sum(ez),
//     write scaled mean-state (192 floats/node).
// ---------------------------------------------------------------------------
__global__ __launch_bounds__(256) void gather_kernel(const float* __restrict__ ez,
                                                     int n_nodes) {
    int lane = threadIdx.x & 31;
    int n = blockIdx.x * 8 + (threadIdx.x >> 5);
    if (n >= n_nodes) return;

    unsigned off = g_off[n];
    int deg = (int)g_deg[n];
    const int2* ep = g_epair + off;

    float4 ah = make_float4(0.f, 0.f, 0.f, 0.f);
    float2 ae = make_float2(0.f, 0.f);

    int i = 0;
    int d4 = deg & ~3;
    for (; i < d4; i += 4) {
        int2 p0 = __ldg(&ep[i + 0]);
        int2 p1 = __ldg(&ep[i + 1]);
        int2 p2 = __ldg(&ep[i + 2]);
        int2 p3 = __ldg(&ep[i + 3]);
        float4 h0 = *reinterpret_cast<const float4*>(&g_hn[(size_t)p0.x * 128 + 4 * lane]);
        float4 h1 = *reinterpret_cast<const float4*>(&g_hn[(size_t)p1.x * 128 + 4 * lane]);
        float4 h2 = *reinterpret_cast<const float4*>(&g_hn[(size_t)p2.x * 128 + 4 * lane]);
        float4 h3 = *reinterpret_cast<const float4*>(&g_hn[(size_t)p3.x * 128 + 4 * lane]);
        float2 e0 = *reinterpret_cast<const float2*>(&ez[(size_t)p0.y * 64 + 2 * lane]);
        float2 e1 = *reinterpret_cast<const float2*>(&ez[(size_t)p1.y * 64 + 2 * lane]);
        float2 e2 = *reinterpret_cast<const float2*>(&ez[(size_t)p2.y * 64 + 2 * lane]);
        float2 e3 = *reinterpret_cast<const float2*>(&ez[(size_t)p3.y * 64 + 2 * lane]);
        ah.x += h0.x + h1.x + h2.x + h3.x;
        ah.y += h0.y + h1.y + h2.y + h3.y;
        ah.z += h0.z + h1.z + h2.z + h3.z;
        ah.w += h0.w + h1.w + h2.w + h3.w;
        ae.x += e0.x + e1.x + e2.x + e3.x;
        ae.y += e0.y + e1.y + e2.y + e3.y;
    }
    for (; i < deg; i++) {
        int2 p = __ldg(&ep[i]);
        float4 h = *reinterpret_cast<const float4*>(&g_hn[(size_t)p.x * 128 + 4 * lane]);
        float2 ev = *reinterpret_cast<const float2*>(&ez[(size_t)p.y * 64 + 2 * lane]);
        ah.x += h.x; ah.y += h.y; ah.z += h.z; ah.w += h.w;
        ae.x += ev.x; ae.y += ev.y;
    }

    float inv = 1.0f / (float)(deg + 1);
    float4 selfh = *reinterpret_cast<const float4*>(&g_hn[(size_t)n * 128 + 4 * lane]);

    float* st = &g_state[(size_t)n * 192];
    *reinterpret_cast<float4*>(&st[4 * lane]) =
        make_float4((selfh.x + ah.x) * inv, (selfh.y + ah.y) * inv,
                    (selfh.z + ah.z) * inv, (selfh.w + ah.w) * inv);
    *reinterpret_cast<float2*>(&st[128 + 2 * lane]) = make_float2(ae.x * inv, ae.y * inv);
    if (lane == 0) g_dinv[n] = (float)deg * inv;
}

// ---------------------------------------------------------------------------
// K6: out = Wr1@s1 + Wc@s2 + dinv*vbe + br ; zero if deg==0
//     (f32x2 packed, 32 nodes x 256 outs per CTA, 128 threads)
// ---------------------------------------------------------------------------
__global__ __launch_bounds__(128) void node_kernel(const float* __restrict__ br,
                                                   float* __restrict__ out,
                                                   int n_nodes) {
    __shared__ __align__(16) float ts[192][34];   // transposed [k][node]
    __shared__ float dinv_s[32];
    __shared__ unsigned deg_s[32];
    int node0 = blockIdx.x * 32;
    int tid = threadIdx.x;

    if (tid < 32) {
        int n = node0 + tid;
        deg_s[tid] = (n < n_nodes) ? g_deg[n] : 0u;
        dinv_s[tid] = (n < n_nodes) ? g_dinv[n] : 0.f;
    }

    for (int i = tid; i < 32 * 48; i += 128) {
        int n = i / 48, c = i % 48;
        int gn = node0 + n;
        float4 v = make_float4(0.f, 0.f, 0.f, 0.f);
        if (gn < n_nodes)
            v = reinterpret_cast<const float4*>(&g_state[(size_t)gn * 192])[c];
        ts[4 * c + 0][n] = v.x;
        ts[4 * c + 1][n] = v.y;
        ts[4 * c + 2][n] = v.z;
        ts[4 * c + 3][n] = v.w;
    }
    __syncthreads();

    int jq = tid & 63;   // output quad (256 outputs)
    int ng = tid >> 6;   // 2 groups x 16 nodes (8 pairs)

    float4 brv = *reinterpret_cast<const float4*>(&br[4 * jq]);
    float4 vb  = *reinterpret_cast<const float4*>(&g_vbe[4 * jq]);

    uint64_t acc[8][4];  // [pair][out]
#pragma unroll
    for (int p = 0; p < 8; p++) {
        float d0 = dinv_s[ng * 16 + 2 * p];
        float d1 = dinv_s[ng * 16 + 2 * p + 1];
        acc[p][0] = pack_f32x2(brv.x + d0 * vb.x, brv.x + d1 * vb.x);
        acc[p][1] = pack_f32x2(brv.y + d0 * vb.y, brv.y + d1 * vb.y);
        acc[p][2] = pack_f32x2(brv.z + d0 * vb.z, brv.z + d1 * vb.z);
        acc[p][3] = pack_f32x2(brv.w + d0 * vb.w, brv.w + d1 * vb.w);
    }

#pragma unroll 2
    for (int k = 0; k < 128; k++) {
        float4 w = *reinterpret_cast<const float4*>(&g_Wr1T[(size_t)k * 256 + 4 * jq]);
        uint64_t wx = dup_f32x2(w.x), wy = dup_f32x2(w.y),
                 wz = dup_f32x2(w.z), ww = dup_f32x2(w.w);
#pragma unroll
        for (int p = 0; p < 8; p++) {
            uint64_t t2 = *reinterpret_cast<const uint64_t*>(&ts[k][ng * 16 + 2 * p]);
            ffma2(acc[p][0], wx, t2);
            ffma2(acc[p][1], wy, t2);
            ffma2(acc[p][2], wz, t2);
            ffma2(acc[p][3], ww, t2);
        }
    }
#pragma unroll 2
    for (int k = 0; k < 64; k++) {
        float4 w = *reinterpret_cast<const float4*>(&g_WcT[(size_t)k * 256 + 4 * jq]);
        uint64_t wx = dup_f32x2(w.x), wy = dup_f32x2(w.y),
                 wz = dup_f32x2(w.z), ww = dup_f32x2(w.w);
#pragma unroll
        for (int p = 0; p < 8; p++) {
            uint64_t t2 = *reinterpret_cast<const uint64_t*>(&ts[128 + k][ng * 16 + 2 * p]);
            ffma2(acc[p][0], wx, t2);
            ffma2(acc[p][1], wy, t2);
            ffma2(acc[p][2], wz, t2);
            ffma2(acc[p][3], ww, t2);
        }
    }

#pragma unroll
    for (int p = 0; p < 8; p++) {
        float2 o0 = unpack_f32x2(acc[p][0]);
        float2 o1 = unpack_f32x2(acc[p][1]);
        float2 o2 = unpack_f32x2(acc[p][2]);
        float2 o3 = unpack_f32x2(acc[p][3]);
        int n = node0 + ng * 16 + 2 * p;
        if (n < n_nodes) {
            float4 o = make_float4(o0.x, o1.x, o2.x, o3.x);
            if (deg_s[ng * 16 + 2 * p] == 0u) o = make_float4(0.f, 0.f, 0.f, 0.f);
            *reinterpret_cast<float4*>(&out[(size_t)n * 256 + 4 * jq]) = o;
        }
        if (n + 1 < n_nodes) {
            float4 o = make_float4(o0.y, o1.y, o2.y, o3.y);
            if (deg_s[ng * 16 + 2 * p + 1] == 0u) o = make_float4(0.f, 0.f, 0.f, 0.f);
            *reinterpret_cast<float4*>(&out[(size_t)(n + 1) * 256 + 4 * jq]) = o;
        }
    }
}

// ---------------------------------------------------------------------------
extern "C" void kernel_launch(void* const* d_in, const int* in_sizes, int n_in,
                              void* d_out, int out_size) {
    const float* x  = (const float*)d_in[0];
    const float* ez = (const float*)d_in[1];
    const int* src  = (const int*)d_in[2];
    const int* dst  = (const int*)d_in[3];
    const float* Wn = (const float*)d_in[4];
    const float* bn = (const float*)d_in[5];
    const float* We = (const float*)d_in[6];
    const float* be = (const float*)d_in[7];
    const float* Wr = (const float*)d_in[8];
    const float* br = (const float*)d_in[9];
    float* out = (float*)d_out;

    int n_nodes = in_sizes[0] / 256;
    int n_edges = in_sizes[2];

    int init_elems = (n_nodes > 128 * 256) ? n_nodes : 128 * 256;
    init_kernel<<<(init_elems + 255) / 256, 256>>>(Wn, Wr, n_nodes);
    wc_kernel<<<256, 64>>>(Wr, We, be);

    int hn_blocks = (n_nodes + 31) / 32;
    hn_count_kernel<<<hn_blocks + 256, 128>>>(x, bn, dst, n_nodes, n_edges, hn_blocks);

    alloc_kernel<<<(n_nodes + 255) / 256, 256>>>(n_nodes);
    fill_kernel<<<1024, 256>>>(src, dst, n_edges);
    gather_kernel<<<(n_nodes + 7) / 8, 256>>>(ez, n_nodes);
    node_kernel<<<(n_nodes + 31) / 32, 128>>>(br, out, n_nodes);
}